// round 1
// baseline (speedup 1.0000x reference)
#include <cuda_runtime.h>
#include <cuda_bf16.h>

// Problem constants
#define B_  16
#define C_  64
#define H_  192
#define W_  192

// Tiling
#define TILE   32   // spatial tile (32x32 output pixels)
#define OCB    16   // output channels per CTA
#define CIC    8    // input-channel chunk held in smem
#define XSP    36   // smem row pitch for x tile (34 used, padded)

// Grid: x = 6*6 = 36 tiles, y = 4 oc blocks, z = 16 batches
// Block: 256 threads = 16x16 threads, each owns a 2x2 pixel micro-tile x 16 oc.

__global__ __launch_bounds__(256, 2)
void conv_interp_kernel(const float* __restrict__ x,
                        const float* __restrict__ DoT,
                        const float* __restrict__ W0,
                        const float* __restrict__ W1,
                        float* __restrict__ y)
{
    __shared__ float s_x[CIC][34 * XSP];        // 8 * 34*36 * 4B = 39168 B
    __shared__ float s_w[CIC][9][OCB];          // 8 * 9 * 16 * 4B =  4608 B

    const int tile  = blockIdx.x;               // 0..35
    const int tx0   = (tile % (W_ / TILE)) * TILE;
    const int ty0   = (tile / (W_ / TILE)) * TILE;
    const int oc0   = blockIdx.y * OCB;
    const int b     = blockIdx.z;

    const int tid = threadIdx.x;
    const int lx  = tid & 15;
    const int ly  = tid >> 4;
    const int px  = lx * 2;                     // pixel x within tile
    const int py  = ly * 2;                     // pixel y within tile

    const float d  = DoT[b];
    const float od = 1.0f - d;

    float acc[OCB][4];
    #pragma unroll
    for (int oc = 0; oc < OCB; oc++) {
        acc[oc][0] = 0.f; acc[oc][1] = 0.f; acc[oc][2] = 0.f; acc[oc][3] = 0.f;
    }

    const float* xb = x + (size_t)b * C_ * H_ * W_;

    for (int ci0 = 0; ci0 < C_; ci0 += CIC) {
        __syncthreads();

        // ---- load x chunk with halo (34x34 per channel), zero-padded ----
        for (int i = tid; i < CIC * 34 * 34; i += 256) {
            int ch  = i / (34 * 34);
            int rem = i - ch * (34 * 34);
            int r   = rem / 34;
            int c   = rem - r * 34;
            int gy  = ty0 - 1 + r;
            int gx  = tx0 - 1 + c;
            float v = 0.f;
            if ((unsigned)gy < H_ && (unsigned)gx < W_) {
                v = xb[((size_t)(ci0 + ch) * H_ + gy) * W_ + gx];
            }
            s_x[ch][r * XSP + c] = v;
        }

        // ---- load + interpolate weight chunk: layout [ci][tap][oc] ----
        for (int i = tid; i < OCB * CIC * 9; i += 256) {
            int ci  = i / (9 * OCB);
            int rem = i - ci * (9 * OCB);
            int tap = rem / OCB;
            int oc  = rem - tap * OCB;
            size_t g = ((size_t)(oc0 + oc) * C_ + (ci0 + ci)) * 9 + tap;
            s_w[ci][tap][oc] = od * W0[g] + d * W1[g];
        }

        __syncthreads();

        // ---- compute ----
        #pragma unroll
        for (int ci = 0; ci < CIC; ci++) {
            float xs[4][4];
            #pragma unroll
            for (int r = 0; r < 4; r++) {
                #pragma unroll
                for (int c = 0; c < 4; c++) {
                    xs[r][c] = s_x[ci][(py + r) * XSP + px + c];
                }
            }
            #pragma unroll
            for (int ky = 0; ky < 3; ky++) {
                #pragma unroll
                for (int kx = 0; kx < 3; kx++) {
                    const float4* wp = (const float4*)&s_w[ci][ky * 3 + kx][0];
                    float4 w0 = wp[0], w1 = wp[1], w2 = wp[2], w3 = wp[3];
                    const float x00 = xs[ky][kx],     x01 = xs[ky][kx + 1];
                    const float x10 = xs[ky + 1][kx], x11 = xs[ky + 1][kx + 1];
                    #define DO_OC(idx, wv)                         \
                        acc[idx][0] += (wv) * x00;                 \
                        acc[idx][1] += (wv) * x01;                 \
                        acc[idx][2] += (wv) * x10;                 \
                        acc[idx][3] += (wv) * x11;
                    DO_OC(0,  w0.x) DO_OC(1,  w0.y) DO_OC(2,  w0.z) DO_OC(3,  w0.w)
                    DO_OC(4,  w1.x) DO_OC(5,  w1.y) DO_OC(6,  w1.z) DO_OC(7,  w1.w)
                    DO_OC(8,  w2.x) DO_OC(9,  w2.y) DO_OC(10, w2.z) DO_OC(11, w2.w)
                    DO_OC(12, w3.x) DO_OC(13, w3.y) DO_OC(14, w3.z) DO_OC(15, w3.w)
                    #undef DO_OC
                }
            }
        }
    }

    // ---- write 16 oc x 2x2 pixels, float2 stores (8B aligned: px even) ----
    float* yb = y + (size_t)b * C_ * H_ * W_;
    #pragma unroll
    for (int oc = 0; oc < OCB; oc++) {
        float* p0 = yb + ((size_t)(oc0 + oc) * H_ + (ty0 + py)) * W_ + (tx0 + px);
        float* p1 = p0 + W_;
        *(float2*)p0 = make_float2(acc[oc][0], acc[oc][1]);
        *(float2*)p1 = make_float2(acc[oc][2], acc[oc][3]);
    }
}

extern "C" void kernel_launch(void* const* d_in, const int* in_sizes, int n_in,
                              void* d_out, int out_size)
{
    const float* x   = (const float*)d_in[0];
    const float* DoT = (const float*)d_in[1];
    const float* W0  = (const float*)d_in[2];
    const float* W1  = (const float*)d_in[3];
    float* y = (float*)d_out;

    dim3 grid((H_ / TILE) * (W_ / TILE), C_ / OCB, B_);
    dim3 block(256);
    conv_interp_kernel<<<grid, block>>>(x, DoT, W0, W1, y);
}